// round 1
// baseline (speedup 1.0000x reference)
#include <cuda_runtime.h>
#include <cuda_bf16.h>
#include <cstdint>

// GRU cell, fused: out = (1-z)*n + z*h
//   r = sigmoid(x@W_ir + h@W_hr + b_r)   -> one accumulator over K=1024 ([x|h]@[W_ir;W_hr])
//   z = sigmoid(x@W_iz + h@W_hz + b_z)   -> one accumulator over K=1024
//   n = tanh(x@W_in + r*(h@W_hn) + b_n)  -> two accumulators (gi_n, gh_n), K=512 each
// Precision: bf16 hi/lo split, 3 mma products per logical product (~2^-17 input error).

#define B_DIM 16384
#define K_DIM 512      // IN == H == 512
#define BM 64
#define BN 64
#define KC 32          // k-chunk per smem stage
#define KW (KC / 2)    // 16 packed bf16x2 words per row
#define KWP (KW + 1)   // +1 word pad against bank conflicts

__device__ __forceinline__ void split_pack2(float a, float b, uint32_t& wh, uint32_t& wl) {
    __nv_bfloat16 ha = __float2bfloat16(a);
    __nv_bfloat16 hb = __float2bfloat16(b);
    float ra = a - __bfloat162float(ha);
    float rb = b - __bfloat162float(hb);
    __nv_bfloat162 th;  th.x = ha;  th.y = hb;
    __nv_bfloat162 tl = __floats2bfloat162_rn(ra, rb);
    wh = *reinterpret_cast<uint32_t*>(&th);
    wl = *reinterpret_cast<uint32_t*>(&tl);
}

__device__ __forceinline__ void split1(float v, uint16_t& hi, uint16_t& lo) {
    __nv_bfloat16 h = __float2bfloat16(v);
    float r = v - __bfloat162float(h);
    __nv_bfloat16 l = __float2bfloat16(r);
    hi = *reinterpret_cast<uint16_t*>(&h);
    lo = *reinterpret_cast<uint16_t*>(&l);
}

__device__ __forceinline__ void mma_bf16(float c[4], const uint32_t a[4], uint32_t b0, uint32_t b1) {
    asm volatile(
        "mma.sync.aligned.m16n8k16.row.col.f32.bf16.bf16.f32 "
        "{%0,%1,%2,%3}, {%4,%5,%6,%7}, {%8,%9}, {%0,%1,%2,%3};\n"
        : "+f"(c[0]), "+f"(c[1]), "+f"(c[2]), "+f"(c[3])
        : "r"(a[0]), "r"(a[1]), "r"(a[2]), "r"(a[3]), "r"(b0), "r"(b1));
}

__global__ void __launch_bounds__(256)
gru_kernel(const float* __restrict__ x, const float* __restrict__ h,
           const float* __restrict__ Wir, const float* __restrict__ Whr, const float* __restrict__ br,
           const float* __restrict__ Wiz, const float* __restrict__ Whz, const float* __restrict__ bz,
           const float* __restrict__ Win, const float* __restrict__ Whn, const float* __restrict__ bn,
           float* __restrict__ out)
{
    // A tile: [row 0..63][k word], packed bf16x2 along k. hi and lo planes.
    __shared__ uint32_t Ah[BM][KWP], Al[BM][KWP];
    // B tiles (3 gates): stored n-major, packed bf16x2 along k -> direct B-fragment loads.
    __shared__ uint32_t Bh[3][BN][KWP], Bl[3][BN][KWP];
    // total smem: (2*64 + 6*64) * 17 * 4 = 34,816 B

    const int tid  = threadIdx.x;
    const int wid  = tid >> 5;
    const int lane = tid & 31;
    const int gid  = lane >> 2;     // 0..7
    const int tig  = lane & 3;      // 0..3
    const int wm   = (wid & 3) << 4;   // warp m offset: 0,16,32,48
    const int wn   = (wid >> 2) << 5;  // warp n offset: 0,32
    const int row0 = blockIdx.x * BM;
    const int col0 = blockIdx.y * BN;

    float acc_r [4][4] = {};   // [ntile][reg], K=1024 combined
    float acc_z [4][4] = {};
    float acc_ni[4][4] = {};   // x@W_in
    float acc_nh[4][4] = {};   // h@W_hn

    #pragma unroll
    for (int phase = 0; phase < 2; ++phase) {
        const float* A  = phase ? h   : x;
        const float* W0 = phase ? Whr : Wir;
        const float* W1 = phase ? Whz : Wiz;
        const float* W2 = phase ? Whn : Win;

        for (int kc = 0; kc < K_DIM; kc += KC) {
            __syncthreads();  // protect smem from previous iteration's readers

            // ---- load A tile: 64 rows x 32 k-cols, fp32 -> bf16 hi/lo packed ----
            #pragma unroll
            for (int it = 0; it < 2; ++it) {
                int idx = tid + it * 256;          // 512 float4 total
                int r   = idx >> 3;                // 0..63
                int c   = (idx & 7) << 2;          // 0..28
                float4 v = *reinterpret_cast<const float4*>(
                    A + (size_t)(row0 + r) * K_DIM + kc + c);
                uint32_t wh0, wl0, wh1, wl1;
                split_pack2(v.x, v.y, wh0, wl0);
                split_pack2(v.z, v.w, wh1, wl1);
                int w = c >> 1;
                Ah[r][w]     = wh0;  Ah[r][w + 1] = wh1;
                Al[r][w]     = wl0;  Al[r][w + 1] = wl1;
            }

            // ---- load 3 B tiles: 32 k-rows x 64 n-cols each, transpose into [n][k] ----
            #pragma unroll
            for (int it = 0; it < 2; ++it) {
                int idx = tid + it * 256;          // 512 float4 per gate
                int k   = idx >> 4;                // 0..31
                int c   = (idx & 15) << 2;         // n offset 0..60
                #pragma unroll
                for (int g = 0; g < 3; ++g) {
                    const float* W = (g == 0) ? W0 : (g == 1) ? W1 : W2;
                    float4 v = *reinterpret_cast<const float4*>(
                        W + (size_t)(kc + k) * K_DIM + col0 + c);
                    uint16_t* ph = reinterpret_cast<uint16_t*>(&Bh[g][0][0]);
                    uint16_t* pl = reinterpret_cast<uint16_t*>(&Bl[g][0][0]);
                    uint16_t hi, lo;
                    split1(v.x, hi, lo); ph[(c + 0) * 2 * KWP + k] = hi; pl[(c + 0) * 2 * KWP + k] = lo;
                    split1(v.y, hi, lo); ph[(c + 1) * 2 * KWP + k] = hi; pl[(c + 1) * 2 * KWP + k] = lo;
                    split1(v.z, hi, lo); ph[(c + 2) * 2 * KWP + k] = hi; pl[(c + 2) * 2 * KWP + k] = lo;
                    split1(v.w, hi, lo); ph[(c + 3) * 2 * KWP + k] = hi; pl[(c + 3) * 2 * KWP + k] = lo;
                }
            }
            __syncthreads();

            // ---- compute: 2 k16 steps per chunk ----
            #pragma unroll
            for (int ks = 0; ks < 2; ++ks) {
                int wb = ks << 3;  // word base: 0 or 8
                uint32_t ah[4], al[4];
                ah[0] = Ah[wm + gid    ][wb + tig    ];
                ah[1] = Ah[wm + gid + 8][wb + tig    ];
                ah[2] = Ah[wm + gid    ][wb + tig + 4];
                ah[3] = Ah[wm + gid + 8][wb + tig + 4];
                al[0] = Al[wm + gid    ][wb + tig    ];
                al[1] = Al[wm + gid + 8][wb + tig    ];
                al[2] = Al[wm + gid    ][wb + tig + 4];
                al[3] = Al[wm + gid + 8][wb + tig + 4];

                #pragma unroll
                for (int nt = 0; nt < 4; ++nt) {
                    int n = wn + (nt << 3) + gid;
                    // gate r
                    {
                        uint32_t bh0 = Bh[0][n][wb + tig], bh1 = Bh[0][n][wb + tig + 4];
                        uint32_t bl0 = Bl[0][n][wb + tig], bl1 = Bl[0][n][wb + tig + 4];
                        mma_bf16(acc_r[nt], ah, bh0, bh1);
                        mma_bf16(acc_r[nt], ah, bl0, bl1);
                        mma_bf16(acc_r[nt], al, bh0, bh1);
                    }
                    // gate z
                    {
                        uint32_t bh0 = Bh[1][n][wb + tig], bh1 = Bh[1][n][wb + tig + 4];
                        uint32_t bl0 = Bl[1][n][wb + tig], bl1 = Bl[1][n][wb + tig + 4];
                        mma_bf16(acc_z[nt], ah, bh0, bh1);
                        mma_bf16(acc_z[nt], ah, bl0, bl1);
                        mma_bf16(acc_z[nt], al, bh0, bh1);
                    }
                    // gate n (phase-split accumulators; phase is compile-time unrolled)
                    {
                        uint32_t bh0 = Bh[2][n][wb + tig], bh1 = Bh[2][n][wb + tig + 4];
                        uint32_t bl0 = Bl[2][n][wb + tig], bl1 = Bl[2][n][wb + tig + 4];
                        if (phase == 0) {
                            mma_bf16(acc_ni[nt], ah, bh0, bh1);
                            mma_bf16(acc_ni[nt], ah, bl0, bl1);
                            mma_bf16(acc_ni[nt], al, bh0, bh1);
                        } else {
                            mma_bf16(acc_nh[nt], ah, bh0, bh1);
                            mma_bf16(acc_nh[nt], ah, bl0, bl1);
                            mma_bf16(acc_nh[nt], al, bh0, bh1);
                        }
                    }
                }
            }
        }
    }

    // ---- epilogue: gates + output ----
    #pragma unroll
    for (int nt = 0; nt < 4; ++nt) {
        #pragma unroll
        for (int i = 0; i < 4; ++i) {
            int rr = row0 + wm + gid + ((i >> 1) << 3);
            int cc = col0 + wn + (nt << 3) + (tig << 1) + (i & 1);
            float pr = acc_r[nt][i] + br[cc];
            float pz = acc_z[nt][i] + bz[cc];
            float rg = 1.0f / (1.0f + __expf(-pr));
            float zg = 1.0f / (1.0f + __expf(-pz));
            float ng = tanhf(acc_ni[nt][i] + rg * acc_nh[nt][i] + bn[cc]);
            float hv = h[(size_t)rr * K_DIM + cc];
            out[(size_t)rr * K_DIM + cc] = (1.0f - zg) * ng + zg * hv;
        }
    }
}

extern "C" void kernel_launch(void* const* d_in, const int* in_sizes, int n_in,
                              void* d_out, int out_size)
{
    const float* x   = (const float*)d_in[0];
    const float* h   = (const float*)d_in[1];
    const float* Wir = (const float*)d_in[2];
    const float* Whr = (const float*)d_in[3];
    const float* br  = (const float*)d_in[4];
    const float* Wiz = (const float*)d_in[5];
    const float* Whz = (const float*)d_in[6];
    const float* bz  = (const float*)d_in[7];
    const float* Win = (const float*)d_in[8];
    const float* Whn = (const float*)d_in[9];
    const float* bn  = (const float*)d_in[10];

    dim3 grid(B_DIM / BM, K_DIM / BN);  // 256 x 8
    gru_kernel<<<grid, 256>>>(x, h, Wir, Whr, br, Wiz, Whz, bz, Win, Whn, bn,
                              (float*)d_out);
}

// round 3
// speedup vs baseline: 1.9750x; 1.9750x over previous
#include <cuda_runtime.h>
#include <cuda_bf16.h>
#include <cstdint>

// ===========================================================================
// GRU cell via mma.sync (sm_103 non-'a' target: tcgen05 unavailable).
// 3-term bf16 split: C = Ah*Bh + Al*Bh + Ah*Bl  (~2^-17 effective precision).
// Pack kernels emit bf16 hi/lo planes in ldmatrix-ready layout; main kernel is
// a 4-accumulator fused GEMM (r, z, n_i, n_h) + gate epilogue.
//   CTA tile M=128 x N=32, 8 warps (4m x 2n), warp tile m32 x n16.
//   K schedule: 32 chunks of k32; chunks 0-15 from x (gi), 16-31 from h (gh).
// ===========================================================================

#define NT_COUNT 16          // 512 / 32
#define MT_COUNT 128         // 16384 / 128

// packed A: [mt 128][chunk 32][plane 2][row 128][64B]  = 64 MB
// packed W: [nt 16][gate 3][chunk 32][plane 2][n 32][64B] = 6 MB
__device__ __align__(128) unsigned char g_Apack[128u * 32u * 2u * 128u * 64u];
__device__ __align__(128) unsigned char g_Wpack[16u * 3u * 32u * 2u * 32u * 64u];

// smem stage layout (stride 80B rows -> conflict-free ldmatrix):
//   A plane p: p*10240 + r*80        (128 rows)
//   B gate g plane p: 20480 + ((g*2+p)*32 + n)*80
#define STAGE_BYTES 35840
#define SMEM_TOTAL (2 * STAGE_BYTES)

__device__ __forceinline__ uint32_t smem_u32(const void* p) {
    uint32_t a;
    asm("{ .reg .u64 t; cvta.to.shared.u64 t, %1; cvt.u32.u64 %0, t; }"
        : "=r"(a) : "l"(p));
    return a;
}

__device__ __forceinline__ void cp16(uint32_t dst, const void* src) {
    asm volatile("cp.async.cg.shared.global [%0], [%1], 16;"
                 :: "r"(dst), "l"(src) : "memory");
}
__device__ __forceinline__ void cp_commit() {
    asm volatile("cp.async.commit_group;" ::: "memory");
}
template <int N> __device__ __forceinline__ void cp_wait() {
    asm volatile("cp.async.wait_group %0;" :: "n"(N) : "memory");
}

__device__ __forceinline__ void ldm4(uint32_t r[4], uint32_t addr) {
    asm volatile("ldmatrix.sync.aligned.m8n8.x4.shared.b16 {%0,%1,%2,%3}, [%4];"
                 : "=r"(r[0]), "=r"(r[1]), "=r"(r[2]), "=r"(r[3]) : "r"(addr));
}

__device__ __forceinline__ void mma16(float c[4], const uint32_t a[4],
                                      uint32_t b0, uint32_t b1) {
    asm volatile(
        "mma.sync.aligned.m16n8k16.row.col.f32.bf16.bf16.f32 "
        "{%0,%1,%2,%3}, {%4,%5,%6,%7}, {%8,%9}, {%0,%1,%2,%3};\n"
        : "+f"(c[0]), "+f"(c[1]), "+f"(c[2]), "+f"(c[3])
        : "r"(a[0]), "r"(a[1]), "r"(a[2]), "r"(a[3]), "r"(b0), "r"(b1));
}

__device__ __forceinline__ uint32_t pack_hi(float a, float b, uint32_t& lo) {
    __nv_bfloat16 ha = __float2bfloat16(a);
    __nv_bfloat16 hb = __float2bfloat16(b);
    float ra = a - __bfloat162float(ha);
    float rb = b - __bfloat162float(hb);
    __nv_bfloat162 hw; hw.x = ha; hw.y = hb;
    __nv_bfloat162 lw = __floats2bfloat162_rn(ra, rb);
    lo = *reinterpret_cast<uint32_t*>(&lw);
    return *reinterpret_cast<uint32_t*>(&hw);
}

// ---------------------------------------------------------------------------
// pack_A: block (c = blockIdx.x in [0,32), mt = blockIdx.y). 256 threads.
__global__ __launch_bounds__(256) void pack_A(const float* __restrict__ x,
                                              const float* __restrict__ hs) {
    const int c = blockIdx.x, mt = blockIdx.y;
    const float* S = (c < 16) ? x : hs;
    const int k0 = (c & 15) * 32;
    const size_t mrow = (size_t)mt * 128;
    unsigned char* hiP = g_Apack + ((size_t)(mt * 32 + c) * 2) * 8192;
    unsigned char* loP = hiP + 8192;
    #pragma unroll
    for (int it = 0; it < 8; ++it) {
        int id = it * 256 + threadIdx.x;   // 2048 float2
        int r = id >> 4, w = id & 15;
        float2 v = *reinterpret_cast<const float2*>(S + (mrow + r) * 512 + k0 + 2 * w);
        uint32_t lo, hi = pack_hi(v.x, v.y, lo);
        *reinterpret_cast<uint32_t*>(hiP + r * 64 + w * 4) = hi;
        *reinterpret_cast<uint32_t*>(loP + r * 64 + w * 4) = lo;
    }
}

// pack_W: block (c = blockIdx.x, ntg = blockIdx.y = nt*3+g). 256 threads.
__global__ __launch_bounds__(256) void pack_W(
    const float* __restrict__ Wir, const float* __restrict__ Whr,
    const float* __restrict__ Wiz, const float* __restrict__ Whz,
    const float* __restrict__ Win, const float* __restrict__ Whn) {
    __shared__ float stg[32][33];
    const int c = blockIdx.x;
    const int nt = blockIdx.y / 3, g = blockIdx.y % 3;
    const float* W = (c < 16)
        ? ((g == 0) ? Wir : (g == 1) ? Wiz : Win)
        : ((g == 0) ? Whr : (g == 1) ? Whz : Whn);
    const int k0 = (c & 15) * 32, n0 = nt * 32;
    {
        int k = threadIdx.x >> 3, n4 = (threadIdx.x & 7) * 4;
        float4 v = *reinterpret_cast<const float4*>(W + (size_t)(k0 + k) * 512 + n0 + n4);
        stg[k][n4] = v.x; stg[k][n4 + 1] = v.y; stg[k][n4 + 2] = v.z; stg[k][n4 + 3] = v.w;
    }
    __syncthreads();
    unsigned char* hiP = g_Wpack + ((size_t)((nt * 3 + g) * 32 + c) * 2) * 2048;
    unsigned char* loP = hiP + 2048;
    {
        int nr = threadIdx.x >> 3, q = threadIdx.x & 7;
        int k = q * 4;
        uint32_t lo0, hi0 = pack_hi(stg[k][nr],     stg[k + 1][nr], lo0);
        uint32_t lo1, hi1 = pack_hi(stg[k + 2][nr], stg[k + 3][nr], lo1);
        *reinterpret_cast<uint32_t*>(hiP + nr * 64 + q * 8)     = hi0;
        *reinterpret_cast<uint32_t*>(hiP + nr * 64 + q * 8 + 4) = hi1;
        *reinterpret_cast<uint32_t*>(loP + nr * 64 + q * 8)     = lo0;
        *reinterpret_cast<uint32_t*>(loP + nr * 64 + q * 8 + 4) = lo1;
    }
}

// ---------------------------------------------------------------------------
__device__ __forceinline__ void issue_stage(uint32_t sbase, int nt, int mt, int c) {
    const int tid = threadIdx.x;
    const unsigned char* Ac = g_Apack + ((size_t)(mt * 32 + c) * 2) * 8192;
    #pragma unroll
    for (int it = 0; it < 4; ++it) {
        int id = it * 256 + tid;            // 1024 ops
        int p = id >> 9, rem = id & 511;
        int r = rem >> 2, ch = rem & 3;
        cp16(sbase + p * 10240 + r * 80 + ch * 16,
             Ac + p * 8192 + r * 64 + ch * 16);
    }
    #pragma unroll
    for (int it = 0; it < 3; ++it) {
        int id = it * 256 + tid;            // 768 ops
        int g = id >> 8, rem = id & 255;
        int p = rem >> 7, rem2 = rem & 127;
        int n = rem2 >> 2, ch = rem2 & 3;
        const unsigned char* Wc = g_Wpack + ((size_t)((nt * 3 + g) * 32 + c) * 2) * 2048;
        cp16(sbase + 20480 + ((g * 2 + p) * 32 + n) * 80 + ch * 16,
             Wc + p * 2048 + n * 64 + ch * 16);
    }
}

#define GATE_MMA(ACC, BH, BL)                                         \
    do {                                                              \
        mma16(ACC[0][0], Ah0, BH[0], BH[1]);                          \
        mma16(ACC[0][1], Ah0, BH[2], BH[3]);                          \
        mma16(ACC[1][0], Ah1, BH[0], BH[1]);                          \
        mma16(ACC[1][1], Ah1, BH[2], BH[3]);                          \
        mma16(ACC[0][0], Al0, BH[0], BH[1]);                          \
        mma16(ACC[0][1], Al0, BH[2], BH[3]);                          \
        mma16(ACC[1][0], Al1, BH[0], BH[1]);                          \
        mma16(ACC[1][1], Al1, BH[2], BH[3]);                          \
        mma16(ACC[0][0], Ah0, BL[0], BL[1]);                          \
        mma16(ACC[0][1], Ah0, BL[2], BL[3]);                          \
        mma16(ACC[1][0], Ah1, BL[0], BL[1]);                          \
        mma16(ACC[1][1], Ah1, BL[2], BL[3]);                          \
    } while (0)

__device__ __forceinline__ void compute_chunk(
    uint32_t sbase, int wm, int wn, int lane,
    float accR[2][2][4], float accZ[2][2][4], float accN[2][2][4]) {
    const int rowA = (lane & 7) + ((lane >> 3) & 1) * 8;
    const int kbA  = (lane >> 4) * 16;
    const int rowB = (lane & 7) + (lane >> 4) * 8;
    const int kbB  = ((lane >> 3) & 1) * 16;
    const uint32_t aAddr = sbase + (wm + rowA) * 80 + kbA;
    const uint32_t bAddr = sbase + 20480 + (wn + rowB) * 80 + kbB;

    #pragma unroll
    for (int ks = 0; ks < 2; ++ks) {
        uint32_t Ah0[4], Ah1[4], Al0[4], Al1[4];
        ldm4(Ah0, aAddr + ks * 32);
        ldm4(Ah1, aAddr + ks * 32 + 1280);          // +16 rows
        ldm4(Al0, aAddr + ks * 32 + 10240);         // lo plane
        ldm4(Al1, aAddr + ks * 32 + 10240 + 1280);

        uint32_t Bh[4], Bl[4];
        // gate r (g=0)
        ldm4(Bh, bAddr + ks * 32);
        ldm4(Bl, bAddr + ks * 32 + 2560);
        GATE_MMA(accR, Bh, Bl);
        // gate z (g=1)
        ldm4(Bh, bAddr + ks * 32 + 5120);
        ldm4(Bl, bAddr + ks * 32 + 7680);
        GATE_MMA(accZ, Bh, Bl);
        // gate n (g=2)
        ldm4(Bh, bAddr + ks * 32 + 10240);
        ldm4(Bl, bAddr + ks * 32 + 12800);
        GATE_MMA(accN, Bh, Bl);
    }
}

__global__ void __launch_bounds__(256) gru_main(
    const float* __restrict__ hs,
    const float* __restrict__ br, const float* __restrict__ bz,
    const float* __restrict__ bn, float* __restrict__ out) {
    extern __shared__ unsigned char smem_raw[];
    const uint32_t smem = smem_u32(smem_raw);

    const int tid = threadIdx.x;
    const int wid = tid >> 5, lane = tid & 31;
    const int wm = (wid & 3) * 32;
    const int wn = (wid >> 2) * 16;
    const int nt = blockIdx.x;     // 0..15
    const int mt = blockIdx.y;     // 0..127

    float aR[2][2][4] = {}, aZ[2][2][4] = {}, aNi[2][2][4] = {}, aNh[2][2][4] = {};

    issue_stage(smem, nt, mt, 0);
    cp_commit();

    for (int c = 0; c < 32; ++c) {
        const uint32_t sbase = smem + (c & 1) * STAGE_BYTES;
        if (c + 1 < 32) {
            issue_stage(smem + ((c + 1) & 1) * STAGE_BYTES, nt, mt, c + 1);
            cp_commit();
            cp_wait<1>();
        } else {
            cp_wait<0>();
        }
        __syncthreads();
        if (c < 16) compute_chunk(sbase, wm, wn, lane, aR, aZ, aNi);
        else        compute_chunk(sbase, wm, wn, lane, aR, aZ, aNh);
        __syncthreads();
    }

    // ---- epilogue ----
    #pragma unroll
    for (int mi = 0; mi < 2; ++mi)
    #pragma unroll
    for (int ni = 0; ni < 2; ++ni)
    #pragma unroll
    for (int i = 0; i < 4; ++i) {
        int rr = mt * 128 + wm + mi * 16 + (lane >> 2) + ((i >> 1) << 3);
        int cc = nt * 32 + wn + ni * 8 + 2 * (lane & 3) + (i & 1);
        float pr = aR[mi][ni][i] + __ldg(br + cc);
        float pz = aZ[mi][ni][i] + __ldg(bz + cc);
        float rg = 1.0f / (1.0f + __expf(-pr));
        float zg = 1.0f / (1.0f + __expf(-pz));
        float ng = tanhf(aNi[mi][ni][i] + rg * aNh[mi][ni][i] + __ldg(bn + cc));
        float hv = hs[(size_t)rr * 512 + cc];
        out[(size_t)rr * 512 + cc] = (1.0f - zg) * ng + zg * hv;
    }
}

// ---------------------------------------------------------------------------
extern "C" void kernel_launch(void* const* d_in, const int* in_sizes, int n_in,
                              void* d_out, int out_size) {
    (void)in_sizes; (void)n_in; (void)out_size;
    const float* x   = (const float*)d_in[0];
    const float* h   = (const float*)d_in[1];
    const float* Wir = (const float*)d_in[2];
    const float* Whr = (const float*)d_in[3];
    const float* br  = (const float*)d_in[4];
    const float* Wiz = (const float*)d_in[5];
    const float* Whz = (const float*)d_in[6];
    const float* bz  = (const float*)d_in[7];
    const float* Win = (const float*)d_in[8];
    const float* Whn = (const float*)d_in[9];
    const float* bn  = (const float*)d_in[10];

    static_assert(SMEM_TOTAL == 71680, "smem layout");
    cudaFuncSetAttribute(gru_main, cudaFuncAttributeMaxDynamicSharedMemorySize,
                         SMEM_TOTAL);

    pack_A<<<dim3(32, 128), 256>>>(x, h);
    pack_W<<<dim3(32, 48), 256>>>(Wir, Whr, Wiz, Whz, Win, Whn);
    gru_main<<<dim3(NT_COUNT, MT_COUNT), 256, SMEM_TOTAL>>>(
        h, br, bz, bn, (float*)d_out);
}

// round 4
// speedup vs baseline: 1.9859x; 1.0055x over previous
#include <cuda_runtime.h>
#include <cuda_bf16.h>
#include <cstdint>

// ===========================================================================
// GRU cell via mma.sync (sm_103 non-'a' target: tcgen05 unavailable).
// 3-term bf16 split: C = Ah*Bh + Al*Bh + Ah*Bl  (~2^-17 effective precision).
// Pack kernels emit bf16 hi/lo planes in ldmatrix-ready layout; main kernel is
// a 4-accumulator fused GEMM (r, z, n_i, n_h) + gate epilogue.
//   CTA tile M=128 x N=32, 8 warps (4m x 2n), warp tile m32 x n16.
//   3-stage cp.async pipeline, ONE __syncthreads per chunk, 2 CTAs/SM.
// ===========================================================================

#define NT_COUNT 16          // 512 / 32
#define MT_COUNT 128         // 16384 / 128
#define NSTAGE 3

// packed A: [mt 128][chunk 32][plane 2][row 128][64B]  = 64 MB
// packed W: [nt 16][gate 3][chunk 32][plane 2][n 32][64B] = 6 MB
__device__ __align__(128) unsigned char g_Apack[128u * 32u * 2u * 128u * 64u];
__device__ __align__(128) unsigned char g_Wpack[16u * 3u * 32u * 2u * 32u * 64u];

// smem stage layout (stride 80B rows -> conflict-free ldmatrix):
//   A plane p: p*10240 + r*80        (128 rows)
//   B gate g plane p: 20480 + ((g*2+p)*32 + n)*80
#define STAGE_BYTES 35840
#define SMEM_TOTAL (NSTAGE * STAGE_BYTES)   // 107520 -> 2 CTAs/SM (210KB/228KB)

__device__ __forceinline__ uint32_t smem_u32(const void* p) {
    uint32_t a;
    asm("{ .reg .u64 t; cvta.to.shared.u64 t, %1; cvt.u32.u64 %0, t; }"
        : "=r"(a) : "l"(p));
    return a;
}

__device__ __forceinline__ void cp16(uint32_t dst, const void* src) {
    asm volatile("cp.async.cg.shared.global [%0], [%1], 16;"
                 :: "r"(dst), "l"(src) : "memory");
}
__device__ __forceinline__ void cp_commit() {
    asm volatile("cp.async.commit_group;" ::: "memory");
}
template <int N> __device__ __forceinline__ void cp_wait() {
    asm volatile("cp.async.wait_group %0;" :: "n"(N) : "memory");
}

__device__ __forceinline__ void ldm4(uint32_t r[4], uint32_t addr) {
    asm volatile("ldmatrix.sync.aligned.m8n8.x4.shared.b16 {%0,%1,%2,%3}, [%4];"
                 : "=r"(r[0]), "=r"(r[1]), "=r"(r[2]), "=r"(r[3]) : "r"(addr));
}

__device__ __forceinline__ void mma16(float c[4], const uint32_t a[4],
                                      uint32_t b0, uint32_t b1) {
    asm volatile(
        "mma.sync.aligned.m16n8k16.row.col.f32.bf16.bf16.f32 "
        "{%0,%1,%2,%3}, {%4,%5,%6,%7}, {%8,%9}, {%0,%1,%2,%3};\n"
        : "+f"(c[0]), "+f"(c[1]), "+f"(c[2]), "+f"(c[3])
        : "r"(a[0]), "r"(a[1]), "r"(a[2]), "r"(a[3]), "r"(b0), "r"(b1));
}

__device__ __forceinline__ uint32_t pack_hi(float a, float b, uint32_t& lo) {
    __nv_bfloat16 ha = __float2bfloat16(a);
    __nv_bfloat16 hb = __float2bfloat16(b);
    float ra = a - __bfloat162float(ha);
    float rb = b - __bfloat162float(hb);
    __nv_bfloat162 hw; hw.x = ha; hw.y = hb;
    __nv_bfloat162 lw = __floats2bfloat162_rn(ra, rb);
    lo = *reinterpret_cast<uint32_t*>(&lw);
    return *reinterpret_cast<uint32_t*>(&hw);
}

// ---------------------------------------------------------------------------
// pack_A: block (c = blockIdx.x in [0,32), mt = blockIdx.y). 256 threads.
__global__ __launch_bounds__(256) void pack_A(const float* __restrict__ x,
                                              const float* __restrict__ hs) {
    const int c = blockIdx.x, mt = blockIdx.y;
    const float* S = (c < 16) ? x : hs;
    const int k0 = (c & 15) * 32;
    const size_t mrow = (size_t)mt * 128;
    unsigned char* hiP = g_Apack + ((size_t)(mt * 32 + c) * 2) * 8192;
    unsigned char* loP = hiP + 8192;
    #pragma unroll
    for (int it = 0; it < 8; ++it) {
        int id = it * 256 + threadIdx.x;   // 2048 float2
        int r = id >> 4, w = id & 15;
        float2 v = *reinterpret_cast<const float2*>(S + (mrow + r) * 512 + k0 + 2 * w);
        uint32_t lo, hi = pack_hi(v.x, v.y, lo);
        *reinterpret_cast<uint32_t*>(hiP + r * 64 + w * 4) = hi;
        *reinterpret_cast<uint32_t*>(loP + r * 64 + w * 4) = lo;
    }
}

// pack_W: block (c = blockIdx.x, ntg = blockIdx.y = nt*3+g). 256 threads.
__global__ __launch_bounds__(256) void pack_W(
    const float* __restrict__ Wir, const float* __restrict__ Whr,
    const float* __restrict__ Wiz, const float* __restrict__ Whz,
    const float* __restrict__ Win, const float* __restrict__ Whn) {
    __shared__ float stg[32][33];
    const int c = blockIdx.x;
    const int nt = blockIdx.y / 3, g = blockIdx.y % 3;
    const float* W = (c < 16)
        ? ((g == 0) ? Wir : (g == 1) ? Wiz : Win)
        : ((g == 0) ? Whr : (g == 1) ? Whz : Whn);
    const int k0 = (c & 15) * 32, n0 = nt * 32;
    {
        int k = threadIdx.x >> 3, n4 = (threadIdx.x & 7) * 4;
        float4 v = *reinterpret_cast<const float4*>(W + (size_t)(k0 + k) * 512 + n0 + n4);
        stg[k][n4] = v.x; stg[k][n4 + 1] = v.y; stg[k][n4 + 2] = v.z; stg[k][n4 + 3] = v.w;
    }
    __syncthreads();
    unsigned char* hiP = g_Wpack + ((size_t)((nt * 3 + g) * 32 + c) * 2) * 2048;
    unsigned char* loP = hiP + 2048;
    {
        int nr = threadIdx.x >> 3, q = threadIdx.x & 7;
        int k = q * 4;
        uint32_t lo0, hi0 = pack_hi(stg[k][nr],     stg[k + 1][nr], lo0);
        uint32_t lo1, hi1 = pack_hi(stg[k + 2][nr], stg[k + 3][nr], lo1);
        *reinterpret_cast<uint32_t*>(hiP + nr * 64 + q * 8)     = hi0;
        *reinterpret_cast<uint32_t*>(hiP + nr * 64 + q * 8 + 4) = hi1;
        *reinterpret_cast<uint32_t*>(loP + nr * 64 + q * 8)     = lo0;
        *reinterpret_cast<uint32_t*>(loP + nr * 64 + q * 8 + 4) = lo1;
    }
}

// ---------------------------------------------------------------------------
__device__ __forceinline__ void issue_stage(uint32_t sbase, int nt, int mt, int c) {
    const int tid = threadIdx.x;
    const unsigned char* Ac = g_Apack + ((size_t)(mt * 32 + c) * 2) * 8192;
    #pragma unroll
    for (int it = 0; it < 4; ++it) {
        int id = it * 256 + tid;            // 1024 ops
        int p = id >> 9, rem = id & 511;
        int r = rem >> 2, ch = rem & 3;
        cp16(sbase + p * 10240 + r * 80 + ch * 16,
             Ac + p * 8192 + r * 64 + ch * 16);
    }
    #pragma unroll
    for (int it = 0; it < 3; ++it) {
        int id = it * 256 + tid;            // 768 ops
        int g = id >> 8, rem = id & 255;
        int p = rem >> 7, rem2 = rem & 127;
        int n = rem2 >> 2, ch = rem2 & 3;
        const unsigned char* Wc = g_Wpack + ((size_t)((nt * 3 + g) * 32 + c) * 2) * 2048;
        cp16(sbase + 20480 + ((g * 2 + p) * 32 + n) * 80 + ch * 16,
             Wc + p * 2048 + n * 64 + ch * 16);
    }
}

#define GATE_MMA(ACC, BH, BL)                                         \
    do {                                                              \
        mma16(ACC[0][0], Ah0, BH[0], BH[1]);                          \
        mma16(ACC[0][1], Ah0, BH[2], BH[3]);                          \
        mma16(ACC[1][0], Ah1, BH[0], BH[1]);                          \
        mma16(ACC[1][1], Ah1, BH[2], BH[3]);                          \
        mma16(ACC[0][0], Al0, BH[0], BH[1]);                          \
        mma16(ACC[0][1], Al0, BH[2], BH[3]);                          \
        mma16(ACC[1][0], Al1, BH[0], BH[1]);                          \
        mma16(ACC[1][1], Al1, BH[2], BH[3]);                          \
        mma16(ACC[0][0], Ah0, BL[0], BL[1]);                          \
        mma16(ACC[0][1], Ah0, BL[2], BL[3]);                          \
        mma16(ACC[1][0], Ah1, BL[0], BL[1]);                          \
        mma16(ACC[1][1], Ah1, BL[2], BL[3]);                          \
    } while (0)

__device__ __forceinline__ void compute_chunk(
    uint32_t sbase, int wm, int wn, int lane,
    float accR[2][2][4], float accZ[2][2][4], float accN[2][2][4]) {
    const int rowA = (lane & 7) + ((lane >> 3) & 1) * 8;
    const int kbA  = (lane >> 4) * 16;
    const int rowB = (lane & 7) + (lane >> 4) * 8;
    const int kbB  = ((lane >> 3) & 1) * 16;
    const uint32_t aAddr = sbase + (wm + rowA) * 80 + kbA;
    const uint32_t bAddr = sbase + 20480 + (wn + rowB) * 80 + kbB;

    #pragma unroll
    for (int ks = 0; ks < 2; ++ks) {
        uint32_t Ah0[4], Ah1[4], Al0[4], Al1[4];
        ldm4(Ah0, aAddr + ks * 32);
        ldm4(Ah1, aAddr + ks * 32 + 1280);          // +16 rows
        ldm4(Al0, aAddr + ks * 32 + 10240);         // lo plane
        ldm4(Al1, aAddr + ks * 32 + 10240 + 1280);

        uint32_t Bh[4], Bl[4];
        // gate r (g=0)
        ldm4(Bh, bAddr + ks * 32);
        ldm4(Bl, bAddr + ks * 32 + 2560);
        GATE_MMA(accR, Bh, Bl);
        // gate z (g=1)
        ldm4(Bh, bAddr + ks * 32 + 5120);
        ldm4(Bl, bAddr + ks * 32 + 7680);
        GATE_MMA(accZ, Bh, Bl);
        // gate n (g=2)
        ldm4(Bh, bAddr + ks * 32 + 10240);
        ldm4(Bl, bAddr + ks * 32 + 12800);
        GATE_MMA(accN, Bh, Bl);
    }
}

__global__ void __launch_bounds__(256, 2) gru_main(
    const float* __restrict__ hs,
    const float* __restrict__ br, const float* __restrict__ bz,
    const float* __restrict__ bn, float* __restrict__ out) {
    extern __shared__ unsigned char smem_raw[];
    const uint32_t smem = smem_u32(smem_raw);

    const int tid = threadIdx.x;
    const int wid = tid >> 5, lane = tid & 31;
    const int wm = (wid & 3) * 32;
    const int wn = (wid >> 2) * 16;
    const int nt = blockIdx.x;     // 0..15
    const int mt = blockIdx.y;     // 0..127

    float aR[2][2][4] = {}, aZ[2][2][4] = {}, aNi[2][2][4] = {}, aNh[2][2][4] = {};

    issue_stage(smem, nt, mt, 0);
    cp_commit();
    issue_stage(smem + STAGE_BYTES, nt, mt, 1);
    cp_commit();

    // Single-sync multistage:
    //   wait(stage c) -> sync (releases buffer (c+2)%3, publishes stage c)
    //   -> issue stage c+2 -> compute stage c.
    int sidx = 0;                  // c % 3
    for (int c = 0; c < 32; ++c) {
        if (c + 2 < 32) cp_wait<1>(); else cp_wait<0>();
        __syncthreads();
        if (c + 2 < 32) {
            int widx = sidx + 2 >= NSTAGE ? sidx + 2 - NSTAGE : sidx + 2;
            issue_stage(smem + widx * STAGE_BYTES, nt, mt, c + 2);
            cp_commit();
        }
        const uint32_t sbase = smem + sidx * STAGE_BYTES;
        if (c < 16) compute_chunk(sbase, wm, wn, lane, aR, aZ, aNi);
        else        compute_chunk(sbase, wm, wn, lane, aR, aZ, aNh);
        sidx = (sidx + 1 >= NSTAGE) ? 0 : sidx + 1;
    }

    // ---- epilogue ----
    #pragma unroll
    for (int mi = 0; mi < 2; ++mi)
    #pragma unroll
    for (int ni = 0; ni < 2; ++ni)
    #pragma unroll
    for (int i = 0; i < 4; ++i) {
        int rr = mt * 128 + wm + mi * 16 + (lane >> 2) + ((i >> 1) << 3);
        int cc = nt * 32 + wn + ni * 8 + 2 * (lane & 3) + (i & 1);
        float pr = aR[mi][ni][i] + __ldg(br + cc);
        float pz = aZ[mi][ni][i] + __ldg(bz + cc);
        float rg = 1.0f / (1.0f + __expf(-pr));
        float zg = 1.0f / (1.0f + __expf(-pz));
        float ng = tanhf(aNi[mi][ni][i] + rg * aNh[mi][ni][i] + __ldg(bn + cc));
        float hv = hs[(size_t)rr * 512 + cc];
        out[(size_t)rr * 512 + cc] = (1.0f - zg) * ng + zg * hv;
    }
}

// ---------------------------------------------------------------------------
extern "C" void kernel_launch(void* const* d_in, const int* in_sizes, int n_in,
                              void* d_out, int out_size) {
    (void)in_sizes; (void)n_in; (void)out_size;
    const float* x   = (const float*)d_in[0];
    const float* h   = (const float*)d_in[1];
    const float* Wir = (const float*)d_in[2];
    const float* Whr = (const float*)d_in[3];
    const float* br  = (const float*)d_in[4];
    const float* Wiz = (const float*)d_in[5];
    const float* Whz = (const float*)d_in[6];
    const float* bz  = (const float*)d_in[7];
    const float* Win = (const float*)d_in[8];
    const float* Whn = (const float*)d_in[9];
    const float* bn  = (const float*)d_in[10];

    static_assert(SMEM_TOTAL == 107520, "smem layout");
    cudaFuncSetAttribute(gru_main, cudaFuncAttributeMaxDynamicSharedMemorySize,
                         SMEM_TOTAL);

    pack_A<<<dim3(32, 128), 256>>>(x, h);
    pack_W<<<dim3(32, 48), 256>>>(Wir, Whr, Wiz, Whz, Win, Whn);
    gru_main<<<dim3(NT_COUNT, MT_COUNT), 256, SMEM_TOTAL>>>(
        h, br, bz, bn, (float*)d_out);
}